// round 5
// baseline (speedup 1.0000x reference)
#include <cuda_runtime.h>

#define BB 4
#define NN 512
#define MM 512
#define DD 128
#define TN 64
#define TM 32

typedef unsigned long long u64;

// ---------------- device scratch (no allocations allowed) ----------------
__device__ float g_z[BB * NN * MM];      // 4 MB pairwise L1 distances
__device__ float g_rmin[BB * NN];
__device__ float g_rinv[BB * NN];
__device__ float g_cmin[BB * MM];
__device__ float g_cinv[BB * MM];
__device__ float g_pnum[BB * NN];
__device__ float g_pden[BB * NN];
__device__ int   g_cnt[BB];

// int32-vs-int64 length sniff (jax canonicalization)
__device__ __forceinline__ int load_len(const void* p, int i) {
    const unsigned* u = (const unsigned*)p;
    if (u[1] == 0u) return (int)((const long long*)p)[i];
    return ((const int*)p)[i];
}

// ---------------- packed f32x2 helpers (Blackwell) ----------------
__device__ __forceinline__ u64 pk2(float lo, float hi) {
    u64 r; asm("mov.b64 %0, {%1, %2};" : "=l"(r) : "f"(lo), "f"(hi)); return r;
}
__device__ __forceinline__ u64 add2(u64 a, u64 b) {
    u64 r; asm("add.rn.f32x2 %0, %1, %2;" : "=l"(r) : "l"(a), "l"(b)); return r;
}
__device__ __forceinline__ void upk2(u64 v, float& lo, float& hi) {
    asm("mov.b64 {%0, %1}, %2;" : "=f"(lo), "=f"(hi) : "l"(v));
}

// ---------------- kernel 1: pairwise L1 distance ----------------
// Grid (16, 8, 4) = 512 blocks; 128 threads; 64n x 32m tile, 4n x 4m micro.
// xs: [d][n] floats (n-pairs read as u64 directly by LDS.128).
// ys2: [d][m] u64, each element pre-negated AND pre-duplicated (-y,-y),
//      so the inner loop is LDS -> add2 -> 2xLOP3 -> add2 with no MOVs.
// m-cols per thread: {tx*2, tx*2+1} and {16+tx*2, 16+tx*2+1} so both ys
// LDS.128 span banks 0-31 exactly (conflict-free).
// Inner loop per d: 3 LDS + 8 add2 + 16 LOP3 + 8 add2 = 35 issues / 16 pairs.
__global__ __launch_bounds__(128) void k_zdiff(
    const float* __restrict__ x, const float* __restrict__ y,
    const void* __restrict__ xlen, const void* __restrict__ ylen) {
    if (blockIdx.x == 0 && blockIdx.y == 0 && blockIdx.z == 0 && threadIdx.x < BB)
        g_cnt[threadIdx.x] = 0;

    int b = blockIdx.z;
    int n0 = blockIdx.y * TN;
    int m0 = blockIdx.x * TM;
    int xl = load_len(xlen, b);
    int yl = load_len(ylen, b);
    if (n0 >= xl || m0 >= yl) return;

    __shared__ float xs[64 * TN];    // 16 KB
    __shared__ u64   ys2[64 * TM];   // 16 KB

    int tid = threadIdx.x;
    int ty = tid >> 3;      // 0..15 -> n micro-group (4 rows)
    int tx = tid & 7;       // 0..7  -> m micro-group (4 cols, split 2+2)

    const float* xb = x + ((size_t)b * NN + n0) * DD;
    const float* yb = y + ((size_t)b * MM + m0) * DD;

    u64 acc[2][4];
#pragma unroll
    for (int i = 0; i < 2; i++)
#pragma unroll
        for (int j = 0; j < 4; j++) acc[i][j] = 0ull;

    const u64 ABSM = 0x7FFFFFFF7FFFFFFFull;

#pragma unroll
    for (int p = 0; p < 2; p++) {
        // stage x: 64 n x 64 d transposed
#pragma unroll
        for (int it = 0; it < 8; it++) {
            int idx = tid + 128 * it;           // 0..1023
            int n  = idx & 63;
            int dq = idx >> 6;                  // 0..15
            const float4 vx = *(const float4*)(xb + (size_t)n * DD + p * 64 + dq * 4);
            xs[(dq * 4 + 0) * TN + n] = vx.x;
            xs[(dq * 4 + 1) * TN + n] = vx.y;
            xs[(dq * 4 + 2) * TN + n] = vx.z;
            xs[(dq * 4 + 3) * TN + n] = vx.w;
        }
        // stage y: negated + duplicated u64
#pragma unroll
        for (int it = 0; it < 4; it++) {
            int idx = tid + 128 * it;           // 0..511
            int m  = idx & 31;
            int dq = idx >> 5;                  // 0..15
            const float4 vy = *(const float4*)(yb + (size_t)m * DD + p * 64 + dq * 4);
            ys2[(dq * 4 + 0) * TM + m] = pk2(-vy.x, -vy.x);
            ys2[(dq * 4 + 1) * TM + m] = pk2(-vy.y, -vy.y);
            ys2[(dq * 4 + 2) * TM + m] = pk2(-vy.z, -vy.z);
            ys2[(dq * 4 + 3) * TM + m] = pk2(-vy.w, -vy.w);
        }
        __syncthreads();

#pragma unroll 4
        for (int d = 0; d < 64; d++) {
            ulonglong2 xv = *(const ulonglong2*)(xs + d * TN + ty * 4);        // n-pairs
            ulonglong2 ya = *(const ulonglong2*)(ys2 + d * TM + tx * 2);       // m 2
            ulonglong2 yb2 = *(const ulonglong2*)(ys2 + d * TM + 16 + tx * 2); // m 2
            u64 t;
            t = add2(xv.x, ya.x)  & ABSM; acc[0][0] = add2(acc[0][0], t);
            t = add2(xv.x, ya.y)  & ABSM; acc[0][1] = add2(acc[0][1], t);
            t = add2(xv.x, yb2.x) & ABSM; acc[0][2] = add2(acc[0][2], t);
            t = add2(xv.x, yb2.y) & ABSM; acc[0][3] = add2(acc[0][3], t);
            t = add2(xv.y, ya.x)  & ABSM; acc[1][0] = add2(acc[1][0], t);
            t = add2(xv.y, ya.y)  & ABSM; acc[1][1] = add2(acc[1][1], t);
            t = add2(xv.y, yb2.x) & ABSM; acc[1][2] = add2(acc[1][2], t);
            t = add2(xv.y, yb2.y) & ABSM; acc[1][3] = add2(acc[1][3], t);
        }
        __syncthreads();
    }

    // unpack: acc[i][j] holds rows (lo, hi) for col j; i=0 -> rows +0/+1, i=1 -> +2/+3
    float lo[2][4], hi[2][4];
#pragma unroll
    for (int i = 0; i < 2; i++)
#pragma unroll
        for (int j = 0; j < 4; j++) upk2(acc[i][j], lo[i][j], hi[i][j]);

    float* zb = g_z + ((size_t)b * NN + n0 + ty * 4) * MM + m0;
    *(float2*)(zb + 0 * MM + tx * 2)      = make_float2(lo[0][0], lo[0][1]);
    *(float2*)(zb + 0 * MM + 16 + tx * 2) = make_float2(lo[0][2], lo[0][3]);
    *(float2*)(zb + 1 * MM + tx * 2)      = make_float2(hi[0][0], hi[0][1]);
    *(float2*)(zb + 1 * MM + 16 + tx * 2) = make_float2(hi[0][2], hi[0][3]);
    *(float2*)(zb + 2 * MM + tx * 2)      = make_float2(lo[1][0], lo[1][1]);
    *(float2*)(zb + 2 * MM + 16 + tx * 2) = make_float2(lo[1][2], lo[1][3]);
    *(float2*)(zb + 3 * MM + tx * 2)      = make_float2(hi[1][0], hi[1][1]);
    *(float2*)(zb + 3 * MM + 16 + tx * 2) = make_float2(hi[1][2], hi[1][3]);
}

// ---------------- kernel 2: fused row + col softmax stats ----------------
// 272 blocks x 256 threads.
//   blocks [0,256): row stats — warp per (b,n) row, float4 + unroll 4.
//   blocks [256,272): col stats — float4 along m (128 cols/block),
//                     8-way row partition, fixed-order reduce.
__global__ __launch_bounds__(256) void k_stats(
    const void* __restrict__ xlen, const void* __restrict__ ylen) {
    int blk = blockIdx.x;
    int tid = threadIdx.x;

    if (blk < 256) {
        // ---- row stats ----
        int lane = tid & 31;
        int wid  = tid >> 5;
        int b = blk >> 6;
        int n = (blk & 63) * 8 + wid;
        int xl = load_len(xlen, b);
        int yl = load_len(ylen, b);
        if (n >= xl) return;

        const float*  zr = g_z + ((size_t)b * NN + n) * MM;
        const float4* z4 = (const float4*)zr;
        int nv4 = yl >> 2;
        int base = yl & ~3;

        float zmin = 3.0e38f;
#pragma unroll 4
        for (int i = lane; i < nv4; i += 32) {
            float4 v = z4[i];
            zmin = fminf(zmin, fminf(fminf(v.x, v.y), fminf(v.z, v.w)));
        }
        if (base + lane < yl) zmin = fminf(zmin, zr[base + lane]);
#pragma unroll
        for (int o = 16; o; o >>= 1) zmin = fminf(zmin, __shfl_xor_sync(0xffffffffu, zmin, o));

        float s = 0.0f;
#pragma unroll 4
        for (int i = lane; i < nv4; i += 32) {
            float4 v = z4[i];
            s += __expf(zmin - v.x) + __expf(zmin - v.y)
               + __expf(zmin - v.z) + __expf(zmin - v.w);
        }
        if (base + lane < yl) s += __expf(zmin - zr[base + lane]);
#pragma unroll
        for (int o = 16; o; o >>= 1) s += __shfl_xor_sync(0xffffffffu, s, o);

        if (lane == 0) {
            g_rmin[b * NN + n] = zmin;
            g_rinv[b * NN + n] = 1.0f / s;
        }
    } else {
        // ---- col stats (vectorized along m) ----
        int cb = blk - 256;             // 0..15
        int b  = cb >> 2;
        int m0 = (cb & 3) * 128;
        int xl = load_len(xlen, b);
        int yl = load_len(ylen, b);
        if (m0 >= yl) return;

        int tx = tid & 31;              // float4 column group
        int tg = tid >> 5;              // 0..7 row partition
        const float* zc = g_z + (size_t)b * NN * MM + m0 + tx * 4;

        __shared__ float4 red4[8][32];
        __shared__ float4 cms[32];

        float4 mn = make_float4(3e38f, 3e38f, 3e38f, 3e38f);
#pragma unroll 4
        for (int n = tg; n < xl; n += 8) {
            float4 v = *(const float4*)(zc + (size_t)n * MM);
            mn.x = fminf(mn.x, v.x); mn.y = fminf(mn.y, v.y);
            mn.z = fminf(mn.z, v.z); mn.w = fminf(mn.w, v.w);
        }
        red4[tg][tx] = mn;
        __syncthreads();
        if (tg == 0) {
            float4 cm = red4[0][tx];
#pragma unroll
            for (int r = 1; r < 8; r++) {
                float4 v = red4[r][tx];
                cm.x = fminf(cm.x, v.x); cm.y = fminf(cm.y, v.y);
                cm.z = fminf(cm.z, v.z); cm.w = fminf(cm.w, v.w);
            }
            cms[tx] = cm;
        }
        __syncthreads();
        float4 cm = cms[tx];
        __syncthreads();

        float4 s = make_float4(0.f, 0.f, 0.f, 0.f);
#pragma unroll 4
        for (int n = tg; n < xl; n += 8) {
            float4 v = *(const float4*)(zc + (size_t)n * MM);
            s.x += __expf(cm.x - v.x); s.y += __expf(cm.y - v.y);
            s.z += __expf(cm.z - v.z); s.w += __expf(cm.w - v.w);
        }
        red4[tg][tx] = s;
        __syncthreads();
        if (tg == 0) {
            float4 t = red4[0][tx];
#pragma unroll
            for (int r = 1; r < 8; r++) {
                float4 v = red4[r][tx];
                t.x += v.x; t.y += v.y; t.z += v.z; t.w += v.w;
            }
            *(float4*)(g_cmin + b * MM + m0 + tx * 4) = cm;
            *(float4*)(g_cinv + b * MM + m0 + tx * 4) =
                make_float4(1.0f / t.x, 1.0f / t.y, 1.0f / t.z, 1.0f / t.w);
        }
    }
}

// ---------------- kernel 3: combine + fused final reduction --------------
__global__ __launch_bounds__(256) void k_accum(
    const void* __restrict__ xlen, const void* __restrict__ ylen,
    float* __restrict__ out) {
    int blk = blockIdx.x;
    int tid = threadIdx.x;
    int lane = tid & 31;
    int wid  = tid >> 5;
    int b = blk >> 6;
    int n = (blk & 63) * 8 + wid;
    int xl = load_len(xlen, b);
    int yl = load_len(ylen, b);

    if (n < xl) {
        const float*  zr  = g_z + ((size_t)b * NN + n) * MM;
        const float4* z4  = (const float4*)zr;
        const float*  cmn = g_cmin + b * MM;
        const float*  civ = g_cinv + b * MM;
        const float4* cm4 = (const float4*)cmn;
        const float4* ci4 = (const float4*)civ;
        float rmin = g_rmin[b * NN + n];
        float rinv = g_rinv[b * NN + n];

        int nv4 = yl >> 2;
        int base = yl & ~3;

        float num = 0.0f, den = 0.0f;
#pragma unroll 4
        for (int i = lane; i < nv4; i += 32) {
            float4 z = z4[i];
            float4 cm = cm4[i];
            float4 ci = ci4[i];
            {
                float beta  = __expf(rmin - z.x) * rinv;
                float alpha = __expf(cm.x - z.x) * ci.x;
                float a = alpha + beta - alpha * beta;
                den += a; num += a * z.x;
            }
            {
                float beta  = __expf(rmin - z.y) * rinv;
                float alpha = __expf(cm.y - z.y) * ci.y;
                float a = alpha + beta - alpha * beta;
                den += a; num += a * z.y;
            }
            {
                float beta  = __expf(rmin - z.z) * rinv;
                float alpha = __expf(cm.z - z.z) * ci.z;
                float a = alpha + beta - alpha * beta;
                den += a; num += a * z.z;
            }
            {
                float beta  = __expf(rmin - z.w) * rinv;
                float alpha = __expf(cm.w - z.w) * ci.w;
                float a = alpha + beta - alpha * beta;
                den += a; num += a * z.w;
            }
        }
        if (base + lane < yl) {
            int m = base + lane;
            float z = zr[m];
            float beta  = __expf(rmin - z) * rinv;
            float alpha = __expf(cmn[m] - z) * civ[m];
            float a = alpha + beta - alpha * beta;
            den += a; num += a * z;
        }
#pragma unroll
        for (int o = 16; o; o >>= 1) {
            num += __shfl_xor_sync(0xffffffffu, num, o);
            den += __shfl_xor_sync(0xffffffffu, den, o);
        }
        if (lane == 0) {
            g_pnum[b * NN + n] = num;
            g_pden[b * NN + n] = den;
        }
    }

    // ---- last-block-done: fused final reduction (deterministic) ----
    __shared__ int s_last;
    __syncthreads();
    if (tid == 0) {
        __threadfence();
        int old = atomicAdd(&g_cnt[b], 1);
        s_last = (old == 63);
    }
    __syncthreads();
    if (!s_last) return;
    __threadfence();

    float num = 0.0f, den = 0.0f;
    for (int i = tid; i < xl; i += 256) {
        num += g_pnum[b * NN + i];
        den += g_pden[b * NN + i];
    }
    __shared__ float sn[256];
    __shared__ float sd[256];
    sn[tid] = num;
    sd[tid] = den;
    __syncthreads();
    for (int s2 = 128; s2; s2 >>= 1) {
        if (tid < s2) {
            sn[tid] += sn[tid + s2];
            sd[tid] += sd[tid + s2];
        }
        __syncthreads();
    }
    if (tid == 0) out[b] = -sn[0] / sd[0];
}

// ---------------- launch ----------------
extern "C" void kernel_launch(void* const* d_in, const int* in_sizes, int n_in,
                              void* d_out, int out_size) {
    const float* x = (const float*)d_in[0];
    const float* y = (const float*)d_in[1];
    const void* xl = d_in[2];
    const void* yl = d_in[3];
    float* out = (float*)d_out;

    dim3 g1(MM / TM, NN / TN, BB);          // (16, 8, 4) = 512 blocks
    k_zdiff<<<g1, 128>>>(x, y, xl, yl);
    k_stats<<<272, 256>>>(xl, yl);
    k_accum<<<256, 256>>>(xl, yl, out);
}

// round 6
// speedup vs baseline: 1.0548x; 1.0548x over previous
#include <cuda_runtime.h>

#define BB 4
#define NN 512
#define MM 512
#define DD 128
#define TN 64
#define TM 32

typedef unsigned long long u64;

// ---------------- device scratch (no allocations allowed) ----------------
__device__ float g_zp[2][BB * NN * MM]; // two 4 MB half-sum buffers (d-split)
__device__ float g_rmin[BB * NN];
__device__ float g_rinv[BB * NN];
__device__ float g_cmin[BB * MM];
__device__ float g_cinv[BB * MM];
__device__ float g_pnum[BB * NN];
__device__ float g_pden[BB * NN];
__device__ int   g_cnt[BB];

// int32-vs-int64 length sniff (jax canonicalization)
__device__ __forceinline__ int load_len(const void* p, int i) {
    const unsigned* u = (const unsigned*)p;
    if (u[1] == 0u) return (int)((const long long*)p)[i];
    return ((const int*)p)[i];
}

// ---------------- packed f32x2 helpers (Blackwell) ----------------
__device__ __forceinline__ u64 pk2(float lo, float hi) {
    u64 r; asm("mov.b64 %0, {%1, %2};" : "=l"(r) : "f"(lo), "f"(hi)); return r;
}
__device__ __forceinline__ u64 add2(u64 a, u64 b) {
    u64 r; asm("add.rn.f32x2 %0, %1, %2;" : "=l"(r) : "l"(a), "l"(b)); return r;
}
__device__ __forceinline__ void upk2(u64 v, float& lo, float& hi) {
    asm("mov.b64 {%0, %1}, %2;" : "=f"(lo), "=f"(hi) : "l"(v));
}

// ---------------- kernel 1: pairwise L1 distance (d-split) ----------------
// Grid (16, 8, 8): blockIdx.z = b*2 + d-phase. 1024 blocks, 128 threads.
// Each block: 64n x 32m tile over 64 of the 128 d, in two 32-d sub-phases
// (16 KB smem -> 7 resident blocks with launch_bounds(128,7); single wave).
// Partial sums go to g_zp[phase]; epilogue reads z0+z1 (order-invariant).
__global__ __launch_bounds__(128, 7) void k_zdiff(
    const float* __restrict__ x, const float* __restrict__ y,
    const void* __restrict__ xlen, const void* __restrict__ ylen) {
    if (blockIdx.x == 0 && blockIdx.y == 0 && blockIdx.z == 0 && threadIdx.x < BB)
        g_cnt[threadIdx.x] = 0;

    int bz = blockIdx.z;
    int b  = bz >> 1;
    int ph = bz & 1;
    int n0 = blockIdx.y * TN;
    int m0 = blockIdx.x * TM;
    int xl = load_len(xlen, b);
    int yl = load_len(ylen, b);
    if (n0 >= xl || m0 >= yl) return;

    __shared__ float xs[32 * TN];    // 8 KB  [d][n]
    __shared__ u64   ys2[32 * TM];   // 8 KB  [d][m], (-y,-y) packed

    int tid = threadIdx.x;
    int ty = tid >> 3;      // 0..15 -> n micro-group (4 rows)
    int tx = tid & 7;       // 0..7  -> m micro-group (4 cols, split 2+2)

    const float* xb = x + ((size_t)b * NN + n0) * DD + ph * 64;
    const float* yb = y + ((size_t)b * MM + m0) * DD + ph * 64;

    u64 acc[2][4];
#pragma unroll
    for (int i = 0; i < 2; i++)
#pragma unroll
        for (int j = 0; j < 4; j++) acc[i][j] = 0ull;

    const u64 ABSM = 0x7FFFFFFF7FFFFFFFull;

#pragma unroll
    for (int sp = 0; sp < 2; sp++) {
        // stage x: 64 n x 32 d transposed
#pragma unroll
        for (int it = 0; it < 4; it++) {
            int idx = tid + 128 * it;           // 0..511
            int n  = idx & 63;
            int dq = idx >> 6;                  // 0..7
            const float4 vx = *(const float4*)(xb + (size_t)n * DD + sp * 32 + dq * 4);
            xs[(dq * 4 + 0) * TN + n] = vx.x;
            xs[(dq * 4 + 1) * TN + n] = vx.y;
            xs[(dq * 4 + 2) * TN + n] = vx.z;
            xs[(dq * 4 + 3) * TN + n] = vx.w;
        }
        // stage y: negated + duplicated u64, 32 m x 32 d
#pragma unroll
        for (int it = 0; it < 2; it++) {
            int idx = tid + 128 * it;           // 0..255
            int m  = idx & 31;
            int dq = idx >> 5;                  // 0..7
            const float4 vy = *(const float4*)(yb + (size_t)m * DD + sp * 32 + dq * 4);
            ys2[(dq * 4 + 0) * TM + m] = pk2(-vy.x, -vy.x);
            ys2[(dq * 4 + 1) * TM + m] = pk2(-vy.y, -vy.y);
            ys2[(dq * 4 + 2) * TM + m] = pk2(-vy.z, -vy.z);
            ys2[(dq * 4 + 3) * TM + m] = pk2(-vy.w, -vy.w);
        }
        __syncthreads();

#pragma unroll 4
        for (int d = 0; d < 32; d++) {
            ulonglong2 xv  = *(const ulonglong2*)(xs + d * TN + ty * 4);
            ulonglong2 ya  = *(const ulonglong2*)(ys2 + d * TM + tx * 2);
            ulonglong2 yb2 = *(const ulonglong2*)(ys2 + d * TM + 16 + tx * 2);
            u64 t;
            t = add2(xv.x, ya.x)  & ABSM; acc[0][0] = add2(acc[0][0], t);
            t = add2(xv.x, ya.y)  & ABSM; acc[0][1] = add2(acc[0][1], t);
            t = add2(xv.x, yb2.x) & ABSM; acc[0][2] = add2(acc[0][2], t);
            t = add2(xv.x, yb2.y) & ABSM; acc[0][3] = add2(acc[0][3], t);
            t = add2(xv.y, ya.x)  & ABSM; acc[1][0] = add2(acc[1][0], t);
            t = add2(xv.y, ya.y)  & ABSM; acc[1][1] = add2(acc[1][1], t);
            t = add2(xv.y, yb2.x) & ABSM; acc[1][2] = add2(acc[1][2], t);
            t = add2(xv.y, yb2.y) & ABSM; acc[1][3] = add2(acc[1][3], t);
        }
        __syncthreads();
    }

    float lo[2][4], hi[2][4];
#pragma unroll
    for (int i = 0; i < 2; i++)
#pragma unroll
        for (int j = 0; j < 4; j++) upk2(acc[i][j], lo[i][j], hi[i][j]);

    float* zb = g_zp[ph] + ((size_t)b * NN + n0 + ty * 4) * MM + m0;
    *(float2*)(zb + 0 * MM + tx * 2)      = make_float2(lo[0][0], lo[0][1]);
    *(float2*)(zb + 0 * MM + 16 + tx * 2) = make_float2(lo[0][2], lo[0][3]);
    *(float2*)(zb + 1 * MM + tx * 2)      = make_float2(hi[0][0], hi[0][1]);
    *(float2*)(zb + 1 * MM + 16 + tx * 2) = make_float2(hi[0][2], hi[0][3]);
    *(float2*)(zb + 2 * MM + tx * 2)      = make_float2(lo[1][0], lo[1][1]);
    *(float2*)(zb + 2 * MM + 16 + tx * 2) = make_float2(lo[1][2], lo[1][3]);
    *(float2*)(zb + 3 * MM + tx * 2)      = make_float2(hi[1][0], hi[1][1]);
    *(float2*)(zb + 3 * MM + 16 + tx * 2) = make_float2(hi[1][2], hi[1][3]);
}

// ---------------- kernel 2: fused row + col softmax stats (R4 shape) -----
// 320 blocks x 256 threads; z = z0 + z1 on the fly.
__global__ __launch_bounds__(256) void k_stats(
    const void* __restrict__ xlen, const void* __restrict__ ylen) {
    int blk = blockIdx.x;
    int tid = threadIdx.x;
    __shared__ float red[8][32];

    if (blk < 256) {
        // ---- row stats ----
        int lane = tid & 31;
        int wid  = tid >> 5;
        int b = blk >> 6;
        int n = (blk & 63) * 8 + wid;
        int xl = load_len(xlen, b);
        int yl = load_len(ylen, b);
        if (n >= xl) return;

        size_t roff = ((size_t)b * NN + n) * MM;
        const float4* z40 = (const float4*)(g_zp[0] + roff);
        const float4* z41 = (const float4*)(g_zp[1] + roff);
        int nv4 = yl >> 2;
        int base = yl & ~3;

        float zmin = 3.0e38f;
#pragma unroll 4
        for (int i = lane; i < nv4; i += 32) {
            float4 a = z40[i], c = z41[i];
            float4 v = make_float4(a.x + c.x, a.y + c.y, a.z + c.z, a.w + c.w);
            zmin = fminf(zmin, fminf(fminf(v.x, v.y), fminf(v.z, v.w)));
        }
        if (base + lane < yl) {
            int m = base + lane;
            zmin = fminf(zmin, g_zp[0][roff + m] + g_zp[1][roff + m]);
        }
#pragma unroll
        for (int o = 16; o; o >>= 1) zmin = fminf(zmin, __shfl_xor_sync(0xffffffffu, zmin, o));

        float s = 0.0f;
#pragma unroll 4
        for (int i = lane; i < nv4; i += 32) {
            float4 a = z40[i], c = z41[i];
            s += __expf(zmin - (a.x + c.x)) + __expf(zmin - (a.y + c.y))
               + __expf(zmin - (a.z + c.z)) + __expf(zmin - (a.w + c.w));
        }
        if (base + lane < yl) {
            int m = base + lane;
            s += __expf(zmin - (g_zp[0][roff + m] + g_zp[1][roff + m]));
        }
#pragma unroll
        for (int o = 16; o; o >>= 1) s += __shfl_xor_sync(0xffffffffu, s, o);

        if (lane == 0) {
            g_rmin[b * NN + n] = zmin;
            g_rinv[b * NN + n] = 1.0f / s;
        }
    } else {
        // ---- col stats ----
        int cblk = blk - 256;           // 0..63
        int b  = cblk >> 4;
        int m0 = (cblk & 15) * 32;
        int xl = load_len(xlen, b);
        int yl = load_len(ylen, b);
        if (m0 >= yl) return;

        int tx = tid & 31;
        int tg = tid >> 5;              // 0..7
        int m = m0 + tx;
        const float* zc0 = g_zp[0] + (size_t)b * NN * MM + m;
        const float* zc1 = g_zp[1] + (size_t)b * NN * MM + m;

        float zmin = 3.0e38f;
        int n = tg;
        for (; n + 24 < xl; n += 32) {
            float a0 = zc0[(size_t)(n     ) * MM] + zc1[(size_t)(n     ) * MM];
            float a1 = zc0[(size_t)(n +  8) * MM] + zc1[(size_t)(n +  8) * MM];
            float a2 = zc0[(size_t)(n + 16) * MM] + zc1[(size_t)(n + 16) * MM];
            float a3 = zc0[(size_t)(n + 24) * MM] + zc1[(size_t)(n + 24) * MM];
            zmin = fminf(zmin, fminf(fminf(a0, a1), fminf(a2, a3)));
        }
        for (; n < xl; n += 8)
            zmin = fminf(zmin, zc0[(size_t)n * MM] + zc1[(size_t)n * MM]);
        red[tg][tx] = zmin;
        __syncthreads();
        if (tg == 0) {
            float cm = red[0][tx];
#pragma unroll
            for (int r = 1; r < 8; r++) cm = fminf(cm, red[r][tx]);
            red[0][tx] = cm;
        }
        __syncthreads();
        float cm = red[0][tx];
        __syncthreads();

        float s = 0.0f;
        n = tg;
        for (; n + 24 < xl; n += 32) {
            float a0 = zc0[(size_t)(n     ) * MM] + zc1[(size_t)(n     ) * MM];
            float a1 = zc0[(size_t)(n +  8) * MM] + zc1[(size_t)(n +  8) * MM];
            float a2 = zc0[(size_t)(n + 16) * MM] + zc1[(size_t)(n + 16) * MM];
            float a3 = zc0[(size_t)(n + 24) * MM] + zc1[(size_t)(n + 24) * MM];
            s += __expf(cm - a0) + __expf(cm - a1) + __expf(cm - a2) + __expf(cm - a3);
        }
        for (; n < xl; n += 8)
            s += __expf(cm - (zc0[(size_t)n * MM] + zc1[(size_t)n * MM]));
        red[tg][tx] = s;
        __syncthreads();
        if (tg == 0) {
            float t = red[0][tx];
#pragma unroll
            for (int r = 1; r < 8; r++) t += red[r][tx];
            g_cmin[b * MM + m] = cm;
            g_cinv[b * MM + m] = 1.0f / t;
        }
    }
}

// ---------------- kernel 3: combine + fused final reduction (R4 shape) ---
__global__ __launch_bounds__(256) void k_accum(
    const void* __restrict__ xlen, const void* __restrict__ ylen,
    float* __restrict__ out) {
    int blk = blockIdx.x;
    int tid = threadIdx.x;
    int lane = tid & 31;
    int wid  = tid >> 5;
    int b = blk >> 6;
    int n = (blk & 63) * 8 + wid;
    int xl = load_len(xlen, b);
    int yl = load_len(ylen, b);

    if (n < xl) {
        size_t roff = ((size_t)b * NN + n) * MM;
        const float4* z40 = (const float4*)(g_zp[0] + roff);
        const float4* z41 = (const float4*)(g_zp[1] + roff);
        const float*  cmn = g_cmin + b * MM;
        const float*  civ = g_cinv + b * MM;
        const float4* cm4 = (const float4*)cmn;
        const float4* ci4 = (const float4*)civ;
        float rmin = g_rmin[b * NN + n];
        float rinv = g_rinv[b * NN + n];

        int nv4 = yl >> 2;
        int base = yl & ~3;

        float num = 0.0f, den = 0.0f;
#pragma unroll 2
        for (int i = lane; i < nv4; i += 32) {
            float4 a = z40[i], c = z41[i];
            float4 z = make_float4(a.x + c.x, a.y + c.y, a.z + c.z, a.w + c.w);
            float4 cm = cm4[i];
            float4 ci = ci4[i];
            {
                float beta  = __expf(rmin - z.x) * rinv;
                float alpha = __expf(cm.x - z.x) * ci.x;
                float av = alpha + beta - alpha * beta;
                den += av; num += av * z.x;
            }
            {
                float beta  = __expf(rmin - z.y) * rinv;
                float alpha = __expf(cm.y - z.y) * ci.y;
                float av = alpha + beta - alpha * beta;
                den += av; num += av * z.y;
            }
            {
                float beta  = __expf(rmin - z.z) * rinv;
                float alpha = __expf(cm.z - z.z) * ci.z;
                float av = alpha + beta - alpha * beta;
                den += av; num += av * z.z;
            }
            {
                float beta  = __expf(rmin - z.w) * rinv;
                float alpha = __expf(cm.w - z.w) * ci.w;
                float av = alpha + beta - alpha * beta;
                den += av; num += av * z.w;
            }
        }
        if (base + lane < yl) {
            int m = base + lane;
            float z = g_zp[0][roff + m] + g_zp[1][roff + m];
            float beta  = __expf(rmin - z) * rinv;
            float alpha = __expf(cmn[m] - z) * civ[m];
            float av = alpha + beta - alpha * beta;
            den += av; num += av * z;
        }
#pragma unroll
        for (int o = 16; o; o >>= 1) {
            num += __shfl_xor_sync(0xffffffffu, num, o);
            den += __shfl_xor_sync(0xffffffffu, den, o);
        }
        if (lane == 0) {
            g_pnum[b * NN + n] = num;
            g_pden[b * NN + n] = den;
        }
    }

    // ---- last-block-done: fused final reduction (deterministic) ----
    __shared__ int s_last;
    __syncthreads();
    if (tid == 0) {
        __threadfence();
        int old = atomicAdd(&g_cnt[b], 1);
        s_last = (old == 63);
    }
    __syncthreads();
    if (!s_last) return;
    __threadfence();

    float num = 0.0f, den = 0.0f;
    for (int i = tid; i < xl; i += 256) {
        num += g_pnum[b * NN + i];
        den += g_pden[b * NN + i];
    }
    __shared__ float sn[256];
    __shared__ float sd[256];
    sn[tid] = num;
    sd[tid] = den;
    __syncthreads();
    for (int s2 = 128; s2; s2 >>= 1) {
        if (tid < s2) {
            sn[tid] += sn[tid + s2];
            sd[tid] += sd[tid + s2];
        }
        __syncthreads();
    }
    if (tid == 0) out[b] = -sn[0] / sd[0];
}

// ---------------- launch ----------------
extern "C" void kernel_launch(void* const* d_in, const int* in_sizes, int n_in,
                              void* d_out, int out_size) {
    const float* x = (const float*)d_in[0];
    const float* y = (const float*)d_in[1];
    const void* xl = d_in[2];
    const void* yl = d_in[3];
    float* out = (float*)d_out;

    dim3 g1(MM / TM, NN / TN, BB * 2);      // (16, 8, 8) = 1024 blocks
    k_zdiff<<<g1, 128>>>(x, y, xl, yl);
    k_stats<<<320, 256>>>(xl, yl);
    k_accum<<<256, 256>>>(xl, yl, out);
}

// round 9
// speedup vs baseline: 1.1846x; 1.1231x over previous
#include <cuda_runtime.h>

#define BB 4
#define NN 512
#define MM 512
#define DD 128
#define TN 64
#define TM 32

typedef unsigned long long u64;

// ---------------- device scratch (no allocations allowed) ----------------
__device__ float g_z [BB * NN * MM];     // 4 MB z[b][n][m]
__device__ float g_zt[BB * MM * NN];     // 4 MB z^T[b][m][n]
__device__ float g_rmin[BB * NN];
__device__ float g_rinv[BB * NN];
__device__ float g_cmin[BB * MM];
__device__ float g_cinv[BB * MM];
__device__ float g_pnum[BB * NN];
__device__ float g_pden[BB * NN];
__device__ int   g_cnt[BB];

// int32-vs-int64 length sniff (jax canonicalization)
__device__ __forceinline__ int load_len(const void* p, int i) {
    const unsigned* u = (const unsigned*)p;
    if (u[1] == 0u) return (int)((const long long*)p)[i];
    return ((const int*)p)[i];
}

// ---------------- packed f32x2 helpers (Blackwell) ----------------
__device__ __forceinline__ u64 pk2(float lo, float hi) {
    u64 r; asm("mov.b64 %0, {%1, %2};" : "=l"(r) : "f"(lo), "f"(hi)); return r;
}
__device__ __forceinline__ u64 add2(u64 a, u64 b) {
    u64 r; asm("add.rn.f32x2 %0, %1, %2;" : "=l"(r) : "l"(a), "l"(b)); return r;
}
__device__ __forceinline__ void upk2(u64 v, float& lo, float& hi) {
    asm("mov.b64 {%0, %1}, %2;" : "=f"(lo), "=f"(hi) : "l"(v));
}

// ---------------- kernel 1: pairwise L1 distance ----------------
// Grid (16, 8, 4) = 512 blocks; 256 threads; 64n x 32m tile, 4n x 2m micro.
// xs: [d][n] floats — LDS.128 gives 2 n-pairs (packed) directly.
// ys2: [d][m] u64, pre-negated AND pre-duplicated (-y,-y) — LDS.128 gives 2 m.
// Inner loop per d: 2 LDS + 4 add2 + 4 LOP3 + 4 add2 = 14 issues / 8 pair-d.
// Epilogue stores BOTH z and z^T (register tile has both orientations).
__global__ __launch_bounds__(256) void k_zdiff(
    const float* __restrict__ x, const float* __restrict__ y,
    const void* __restrict__ xlen, const void* __restrict__ ylen) {
    if (blockIdx.x == 0 && blockIdx.y == 0 && blockIdx.z == 0 && threadIdx.x < BB)
        g_cnt[threadIdx.x] = 0;

    int b = blockIdx.z;
    int n0 = blockIdx.y * TN;
    int m0 = blockIdx.x * TM;
    int xl = load_len(xlen, b);
    int yl = load_len(ylen, b);
    if (n0 >= xl || m0 >= yl) return;

    __shared__ float xs[64 * TN];    // 16 KB  [d][n] (64-d phase)
    __shared__ u64   ys2[64 * TM];   // 16 KB  [d][m], (-y,-y) packed

    int tid = threadIdx.x;
    int ty = tid >> 4;      // 0..15 -> n micro-group (4 rows)
    int tx = tid & 15;      // 0..15 -> m micro-group (2 cols)

    const float* xb = x + ((size_t)b * NN + n0) * DD;
    const float* yb = y + ((size_t)b * MM + m0) * DD;

    u64 acc[2][2];          // [n-pair][m]
    acc[0][0] = acc[0][1] = acc[1][0] = acc[1][1] = 0ull;

    const u64 ABSM = 0x7FFFFFFF7FFFFFFFull;

#pragma unroll
    for (int p = 0; p < 2; p++) {
        // stage x: 64 n x 64 d transposed
#pragma unroll
        for (int it = 0; it < 4; it++) {
            int idx = tid + 256 * it;           // 0..1023
            int n  = idx & 63;
            int dq = idx >> 6;                  // 0..15
            const float4 vx = *(const float4*)(xb + (size_t)n * DD + p * 64 + dq * 4);
            xs[(dq * 4 + 0) * TN + n] = vx.x;
            xs[(dq * 4 + 1) * TN + n] = vx.y;
            xs[(dq * 4 + 2) * TN + n] = vx.z;
            xs[(dq * 4 + 3) * TN + n] = vx.w;
        }
        // stage y: negated + duplicated u64, 32 m x 64 d
#pragma unroll
        for (int it = 0; it < 2; it++) {
            int idx = tid + 256 * it;           // 0..511
            int m  = idx & 31;
            int dq = idx >> 5;                  // 0..15
            const float4 vy = *(const float4*)(yb + (size_t)m * DD + p * 64 + dq * 4);
            ys2[(dq * 4 + 0) * TM + m] = pk2(-vy.x, -vy.x);
            ys2[(dq * 4 + 1) * TM + m] = pk2(-vy.y, -vy.y);
            ys2[(dq * 4 + 2) * TM + m] = pk2(-vy.z, -vy.z);
            ys2[(dq * 4 + 3) * TM + m] = pk2(-vy.w, -vy.w);
        }
        __syncthreads();

#pragma unroll 4
        for (int d = 0; d < 64; d++) {
            ulonglong2 xv = *(const ulonglong2*)(xs + d * TN + ty * 4);   // 2 n-pairs
            ulonglong2 yv = *(const ulonglong2*)(ys2 + d * TM + tx * 2);  // 2 m (dup)
            u64 t;
            t = add2(xv.x, yv.x) & ABSM; acc[0][0] = add2(acc[0][0], t);
            t = add2(xv.x, yv.y) & ABSM; acc[0][1] = add2(acc[0][1], t);
            t = add2(xv.y, yv.x) & ABSM; acc[1][0] = add2(acc[1][0], t);
            t = add2(xv.y, yv.y) & ABSM; acc[1][1] = add2(acc[1][1], t);
        }
        __syncthreads();
    }

    // unpack: acc[i][j] = rows (n+2i, n+2i+1) x col (m+j)
    float v00l, v00h, v01l, v01h, v10l, v10h, v11l, v11h;
    upk2(acc[0][0], v00l, v00h);
    upk2(acc[0][1], v01l, v01h);
    upk2(acc[1][0], v10l, v10h);
    upk2(acc[1][1], v11l, v11h);

    // z store: 4 rows x float2
    float* zb = g_z + ((size_t)b * NN + n0 + ty * 4) * MM + m0 + tx * 2;
    *(float2*)(zb + 0 * MM) = make_float2(v00l, v01l);
    *(float2*)(zb + 1 * MM) = make_float2(v00h, v01h);
    *(float2*)(zb + 2 * MM) = make_float2(v10l, v11l);
    *(float2*)(zb + 3 * MM) = make_float2(v10h, v11h);

    // z^T store: 2 m-rows x float4 (4 consecutive n)
    float* ztb = g_zt + ((size_t)b * MM + m0 + tx * 2) * NN + n0 + ty * 4;
    *(float4*)(ztb + 0 * NN) = make_float4(v00l, v00h, v10l, v10h);
    *(float4*)(ztb + 1 * NN) = make_float4(v01l, v01h, v11l, v11h);
}

// ---------------- kernel 2: unified row + col softmax stats --------------
// 512 blocks x 256 threads, 8 warps/block -> 4096 warp-rows:
//   w in [0,2048):    z rows   (b, n): guard n<xl, loop yl -> rmin/rinv
//   w in [2048,4096): z^T rows (b, m): guard m<yl, loop xl -> cmin/cinv
// Identical coalesced float4 path for both.
__global__ __launch_bounds__(256) void k_stats(
    const void* __restrict__ xlen, const void* __restrict__ ylen) {
    int w = blockIdx.x * 8 + (threadIdx.x >> 5);
    int lane = threadIdx.x & 31;

    const float* src;
    float* omin; float* oinv;
    int len;
    if (w < 2048) {
        int b = w >> 9, n = w & 511;
        if (n >= load_len(xlen, b)) return;
        len = load_len(ylen, b);
        src = g_z + ((size_t)b * NN + n) * MM;
        omin = g_rmin + b * NN + n;
        oinv = g_rinv + b * NN + n;
    } else {
        int w2 = w - 2048;
        int b = w2 >> 9, m = w2 & 511;
        if (m >= load_len(ylen, b)) return;
        len = load_len(xlen, b);
        src = g_zt + ((size_t)b * MM + m) * NN;
        omin = g_cmin + b * MM + m;
        oinv = g_cinv + b * MM + m;
    }

    const float4* s4 = (const float4*)src;
    int nv4 = len >> 2;
    int base = len & ~3;

    float zmin = 3.0e38f;
#pragma unroll 4
    for (int i = lane; i < nv4; i += 32) {
        float4 v = s4[i];
        zmin = fminf(zmin, fminf(fminf(v.x, v.y), fminf(v.z, v.w)));
    }
    if (base + lane < len) zmin = fminf(zmin, src[base + lane]);
#pragma unroll
    for (int o = 16; o; o >>= 1) zmin = fminf(zmin, __shfl_xor_sync(0xffffffffu, zmin, o));

    float s = 0.0f;
#pragma unroll 4
    for (int i = lane; i < nv4; i += 32) {
        float4 v = s4[i];
        s += __expf(zmin - v.x) + __expf(zmin - v.y)
           + __expf(zmin - v.z) + __expf(zmin - v.w);
    }
    if (base + lane < len) s += __expf(zmin - src[base + lane]);
#pragma unroll
    for (int o = 16; o; o >>= 1) s += __shfl_xor_sync(0xffffffffu, s, o);

    if (lane == 0) {
        *omin = zmin;
        *oinv = 1.0f / s;
    }
}

// ---------------- kernel 3: combine + fused final reduction --------------
// 512 blocks x 128 threads; warp per (b,n) row.
__global__ __launch_bounds__(128) void k_accum(
    const void* __restrict__ xlen, const void* __restrict__ ylen,
    float* __restrict__ out) {
    int blk = blockIdx.x;
    int tid = threadIdx.x;
    int lane = tid & 31;
    int wid  = tid >> 5;
    int b = blk >> 7;
    int n = (blk & 127) * 4 + wid;
    int xl = load_len(xlen, b);
    int yl = load_len(ylen, b);

    if (n < xl) {
        const float*  zr  = g_z + ((size_t)b * NN + n) * MM;
        const float4* z4  = (const float4*)zr;
        const float*  cmn = g_cmin + b * MM;
        const float*  civ = g_cinv + b * MM;
        const float4* cm4 = (const float4*)cmn;
        const float4* ci4 = (const float4*)civ;
        float rmin = g_rmin[b * NN + n];
        float rinv = g_rinv[b * NN + n];

        int nv4 = yl >> 2;
        int base = yl & ~3;

        float num = 0.0f, den = 0.0f;
#pragma unroll 4
        for (int i = lane; i < nv4; i += 32) {
            float4 z = z4[i];
            float4 cm = cm4[i];
            float4 ci = ci4[i];
            {
                float beta  = __expf(rmin - z.x) * rinv;
                float alpha = __expf(cm.x - z.x) * ci.x;
                float a = alpha + beta - alpha * beta;
                den += a; num += a * z.x;
            }
            {
                float beta  = __expf(rmin - z.y) * rinv;
                float alpha = __expf(cm.y - z.y) * ci.y;
                float a = alpha + beta - alpha * beta;
                den += a; num += a * z.y;
            }
            {
                float beta  = __expf(rmin - z.z) * rinv;
                float alpha = __expf(cm.z - z.z) * ci.z;
                float a = alpha + beta - alpha * beta;
                den += a; num += a * z.z;
            }
            {
                float beta  = __expf(rmin - z.w) * rinv;
                float alpha = __expf(cm.w - z.w) * ci.w;
                float a = alpha + beta - alpha * beta;
                den += a; num += a * z.w;
            }
        }
        if (base + lane < yl) {
            int m = base + lane;
            float z = zr[m];
            float beta  = __expf(rmin - z) * rinv;
            float alpha = __expf(cmn[m] - z) * civ[m];
            float a = alpha + beta - alpha * beta;
            den += a; num += a * z;
        }
#pragma unroll
        for (int o = 16; o; o >>= 1) {
            num += __shfl_xor_sync(0xffffffffu, num, o);
            den += __shfl_xor_sync(0xffffffffu, den, o);
        }
        if (lane == 0) {
            g_pnum[b * NN + n] = num;
            g_pden[b * NN + n] = den;
        }
    }

    // ---- last-block-done: fused final reduction (deterministic) ----
    __shared__ int s_last;
    __syncthreads();
    if (tid == 0) {
        __threadfence();
        int old = atomicAdd(&g_cnt[b], 1);
        s_last = (old == 127);
    }
    __syncthreads();
    if (!s_last) return;
    __threadfence();

    float num = 0.0f, den = 0.0f;
    for (int i = tid; i < xl; i += 128) {
        num += g_pnum[b * NN + i];
        den += g_pden[b * NN + i];
    }
    __shared__ float sn[128];
    __shared__ float sd[128];
    sn[tid] = num;
    sd[tid] = den;
    __syncthreads();
    for (int s2 = 64; s2; s2 >>= 1) {
        if (tid < s2) {
            sn[tid] += sn[tid + s2];
            sd[tid] += sd[tid + s2];
        }
        __syncthreads();
    }
    if (tid == 0) out[b] = -sn[0] / sd[0];
}

// ---------------- launch ----------------
extern "C" void kernel_launch(void* const* d_in, const int* in_sizes, int n_in,
                              void* d_out, int out_size) {
    const float* x = (const float*)d_in[0];
    const float* y = (const float*)d_in[1];
    const void* xl = d_in[2];
    const void* yl = d_in[3];
    float* out = (float*)d_out;

    dim3 g1(MM / TM, NN / TN, BB);          // (16, 8, 4) = 512 blocks
    k_zdiff<<<g1, 256>>>(x, y, xl, yl);
    k_stats<<<512, 256>>>(xl, yl);
    k_accum<<<512, 128>>>(xl, yl, out);
}